// round 16
// baseline (speedup 1.0000x reference)
#include <cuda_runtime.h>
#include <cuda_bf16.h>
#include <math.h>

// N=16384 nodes, L=8, D=256, H=256, R=64. Gate order i,f,g,o.
// Fused recurrence: gates_t = [h_{t-1} | x_t] @ [Whh | Wih]^T + b (K=512 GEMM
// per step; t=0 x-only K=256). INT8 exact 16-bit fixed-point path:
// A = Ah*256+Al, B = Bh*256+Bl (s8 limbs), 4 products on
// mma.sync.m16n8k32.s8 (2x MACs/instr vs bf16), int32 limb accumulators
// folded into fp32 master per (mi, ni-pair) per chunk (exact pow2 FFMAs).
// Scales: h 2^-14, x/rel 2^-12, W 2^-16. XOR-swizzled 32B-row smem,
// 2-stage cp.async, ldmatrix loads, register cell-update epilogue.

#define NT 256

// ------------------------- device scratch (no allocs) -----------------------
__device__ float g_c[8388608];             // [2][16384][256] cell state fp32
__device__ signed char g_h8h[16777216];    // [2 lstm][2 buf][16384][256]
__device__ signed char g_h8l[16777216];
__device__ signed char g_x8h[67108864];    // [2 chain][16384*8 (n*8+l)][256]
__device__ signed char g_x8l[67108864];
__device__ signed char g_w8h[1048576];     // [2][8 strip][128(g*32+jj)][512(Whh|Wih)]
__device__ signed char g_w8l[1048576];
__device__ signed char g_we8h[147456];     // [256][576]
__device__ signed char g_we8l[147456];
__device__ signed char g_r8h[1048576];     // [16384][64]
__device__ signed char g_r8l[1048576];
__device__ float g_bsum[2048];             // [2][1024] bih+bhh

// fold scales: s_a * s_w
#define S_HW (1.0f / 1073741824.0f)  // 2^-14 * 2^-16
#define S_XW (1.0f / 268435456.0f)   // 2^-12 * 2^-16

// ------------------------------- helpers ------------------------------------
__device__ __forceinline__ float fsig(float x) {
  return __fdividef(1.0f, 1.0f + __expf(-x));
}
__device__ __forceinline__ float ftanh(float x) {
  return 2.0f * __fdividef(1.0f, 1.0f + __expf(-2.0f * x)) - 1.0f;
}

__device__ __forceinline__ void mma_s8(int* d, const unsigned* a, const unsigned* b) {
  asm volatile(
      "mma.sync.aligned.m16n8k32.row.col.s32.s8.s8.s32 "
      "{%0,%1,%2,%3}, {%4,%5,%6,%7}, {%8,%9}, {%0,%1,%2,%3};\n"
      : "+r"(d[0]), "+r"(d[1]), "+r"(d[2]), "+r"(d[3])
      : "r"(a[0]), "r"(a[1]), "r"(a[2]), "r"(a[3]), "r"(b[0]), "r"(b[1]));
}
__device__ __forceinline__ void ldsm4(unsigned* r, const void* p) {
  unsigned a = (unsigned)__cvta_generic_to_shared(p);
  asm volatile("ldmatrix.sync.aligned.m8n8.x4.shared.b16 {%0,%1,%2,%3}, [%4];\n"
               : "=r"(r[0]), "=r"(r[1]), "=r"(r[2]), "=r"(r[3]) : "r"(a));
}
__device__ __forceinline__ void cpa16(void* dst, const void* src) {
  unsigned s = (unsigned)__cvta_generic_to_shared(dst);
  asm volatile("cp.async.cg.shared.global [%0], [%1], 16;\n" :: "r"(s), "l"(src));
}
#define CP_COMMIT asm volatile("cp.async.commit_group;\n")
template <int N>
__device__ __forceinline__ void cp_wait() {
  asm volatile("cp.async.wait_group %0;\n" :: "n"(N));
}

// XOR-swizzled smem: array [128 rows][32 bytes]; seg s in {0,1} (16B each).
// (2r + s') mod 8 distinct over any 8 consecutive rows -> conflict-free ldsm.
#define SWZ8(r, s) ((r) * 32 + ((((s) ^ ((r) >> 2)) & 1) << 4))
// per-stage buffer: Ah[4K] Al[4K] Bh[4K] Bl[4K] = 16KB
#define A_HI 0
#define A_LO 4096
#define B_HI 8192
#define B_LO 12288
#define BUFSZ 16384
#define SMEM_BYTES 32768  // 2 stages

// 16-bit quantize + limb split: q in [-32639,32639], hi = round(q/256) s8,
// lo = q - hi*256 in [-128,127].
__device__ __forceinline__ void qsplit(float v, float s, int& hi, int& lo) {
  int q = __float2int_rn(v * s);
  q = max(-32639, min(32639, q));
  hi = (q + 128) >> 8;
  lo = q - (hi << 8);
}

// GM=true: B smem row c = ni*32 + wn*8 + lr (gate-major); false: wn*32 + ni*8.
// B hi/lo merged in one ldsm4 (lanes 0-15: Bh seg0/1, 16-31: Bl seg0/1).
// Per (mi, ni-pair): 8 IMMA into int accs (hh/mid/ll), immediate exact fold
// into fp32 master: acc += s * (65536*hh + 256*mid + ll).
template <bool GM>
__device__ __forceinline__ void compute_chunk_i8(
    const signed char* ahi, const signed char* alo,
    const signed char* bhi, const signed char* blo,
    float acc[4][4][4], float scale, int wm, int wn, int lane) {
  const int lr = lane & 7;
  const int arow = lr + ((lane >> 3) & 1) * 8;
  const int asg = lane >> 4;
  const signed char* bsrc = (lane >= 16) ? blo : bhi;
  const int bsg = (lane >> 3) & 1;
  unsigned bb[4][4];
#pragma unroll
  for (int ni = 0; ni < 4; ni++) {
    int c = (GM ? ni * 32 + wn * 8 : wn * 32 + ni * 8) + lr;
    ldsm4(bb[ni], bsrc + SWZ8(c, bsg));
  }
#pragma unroll
  for (int mi = 0; mi < 4; mi++) {
    int r = wm * 64 + mi * 16 + arow;
    unsigned ah[4], al[4];
    ldsm4(ah, ahi + SWZ8(r, asg));
    ldsm4(al, alo + SWZ8(r, asg));
#pragma unroll
    for (int nh = 0; nh < 2; nh++) {
      int hh[2][4] = {{0, 0, 0, 0}, {0, 0, 0, 0}};
      int md[2][4] = {{0, 0, 0, 0}, {0, 0, 0, 0}};
      int ll[2][4] = {{0, 0, 0, 0}, {0, 0, 0, 0}};
#pragma unroll
      for (int nj = 0; nj < 2; nj++) {
        int ni = nh * 2 + nj;
        mma_s8(hh[nj], ah, &bb[ni][0]);
        mma_s8(md[nj], ah, &bb[ni][2]);
        mma_s8(md[nj], al, &bb[ni][0]);
        mma_s8(ll[nj], al, &bb[ni][2]);
      }
#pragma unroll
      for (int nj = 0; nj < 2; nj++) {
        int ni = nh * 2 + nj;
#pragma unroll
        for (int e = 0; e < 4; e++) {
          float f = fmaf(65536.0f, (float)hh[nj][e],
                         fmaf(256.0f, (float)md[nj][e], (float)ll[nj][e]));
          acc[mi][ni][e] = fmaf(scale, f, acc[mi][ni][e]);
        }
      }
    }
  }
}

// quantize h (|h|<1) at 2^-14 and store limb pair for 2 adjacent j's
__device__ __forceinline__ void st_q2(signed char* ph, signed char* pl,
                                      float x, float y) {
  int qx = __float2int_rn(x * 16384.0f);
  int qy = __float2int_rn(y * 16384.0f);
  int hx = (qx + 128) >> 8, hy = (qy + 128) >> 8;
  char2 h2, l2;
  h2.x = (signed char)hx; h2.y = (signed char)hy;
  l2.x = (signed char)(qx - (hx << 8)); l2.y = (signed char)(qy - (hy << 8));
  *(char2*)ph = h2;
  *(char2*)pl = l2;
}

// ---------------------------------------------------------------------------
// Split/quantize kernels (run every call; deterministic)
// ---------------------------------------------------------------------------
__global__ void k_split_x(const float* __restrict__ xl, const float* __restrict__ xr) {
  long i = (long)blockIdx.x * NT + threadIdx.x;  // [0, 16777216) float4 groups
  long chain = i >> 23;
  long j = i & 8388607;
  float4 v = *(const float4*)((chain ? xr : xl) + j * 4);
  long o = chain * 33554432 + j * 4;
  float x[4] = {v.x, v.y, v.z, v.w};
  char4 h4, l4;
  int hi, lo;
  qsplit(x[0], 4096.0f, hi, lo); h4.x = (signed char)hi; l4.x = (signed char)lo;
  qsplit(x[1], 4096.0f, hi, lo); h4.y = (signed char)hi; l4.y = (signed char)lo;
  qsplit(x[2], 4096.0f, hi, lo); h4.z = (signed char)hi; l4.z = (signed char)lo;
  qsplit(x[3], 4096.0f, hi, lo); h4.w = (signed char)hi; l4.w = (signed char)lo;
  *(char4*)(g_x8h + o) = h4;
  *(char4*)(g_x8l + o) = l4;
}

__global__ void k_split_misc(const float* __restrict__ Whh_l, const float* __restrict__ Whh_r,
                             const float* __restrict__ Wih_l, const float* __restrict__ Wih_r,
                             const float* __restrict__ Wenc, const float* __restrict__ rel,
                             const float* __restrict__ bih_l, const float* __restrict__ bhh_l,
                             const float* __restrict__ bih_r, const float* __restrict__ bhh_r) {
  long idx = (long)blockIdx.x * NT + threadIdx.x;
  if (idx < 1048576) {
    // Wcomb gather: dst (((z*8+strip)*128 + (g*32+jj))*512 + k
    int k = (int)(idx & 511);
    long r2 = idx >> 9;
    int row = (int)(r2 & 127);
    int zs = (int)(r2 >> 7);
    int strip = zs & 7, z = zs >> 3;
    int g = row >> 5, jj = row & 31;
    long wrow = (long)(g * 256 + strip * 32 + jj) * 256;
    float v;
    if (k < 256) v = (z ? Whh_r : Whh_l)[wrow + k];
    else         v = (z ? Wih_r : Wih_l)[wrow + k - 256];
    int hi, lo;
    qsplit(v, 65536.0f, hi, lo);
    g_w8h[idx] = (signed char)hi;
    g_w8l[idx] = (signed char)lo;
  } else if (idx < 1196032) {
    long j = idx - 1048576;
    int hi, lo;
    qsplit(Wenc[j], 65536.0f, hi, lo);
    g_we8h[j] = (signed char)hi;
    g_we8l[j] = (signed char)lo;
  } else if (idx < 2244608) {
    long j = idx - 1196032;
    int hi, lo;
    qsplit(rel[j], 4096.0f, hi, lo);
    g_r8h[j] = (signed char)hi;
    g_r8l[j] = (signed char)lo;
  } else if (idx < 2246656) {
    long j = idx - 2244608;  // [0,2048)
    int z = (int)(j >> 10);
    int cc = (int)(j & 1023);
    g_bsum[j] = (z ? bih_r[cc] : bih_l[cc]) + (z ? bhh_r[cc] : bhh_l[cc]);
  }
}

// ---------------------------------------------------------------------------
// Fused recurrent step t (0..7): gates = [h_{t-1} | x_t] @ Wcomb^T + bsum.
// grid (strip=8, rowTile=128, z=2), 256 threads, 2 CTAs/SM. K=512 = 16 chunks
// (8 h + 8 x); t=0 skips the h chunks (h0=0). 2-stage cp.async pipeline.
// Gate-major fragment map (ni=gate): register cell-update epilogue.
// ---------------------------------------------------------------------------
__device__ __forceinline__ void step_stage8(signed char* base, long rowBase,
                                            long bRow, int kc, int t, int z, int tid) {
  int r = tid >> 1, sg = tid & 1;
  int d = SWZ8(r, sg);
  const signed char *sh, *sl;
  long aoff;
  if (kc < 8) {
    long o = ((long)z * 2 + (t & 1)) * 4194304;
    sh = g_h8h + o; sl = g_h8l + o;
    aoff = (rowBase + r) * 256L + kc * 32 + sg * 16;
  } else {
    long o = (long)z * 33554432 + t * 256;  // row n -> (n*8+t)*256
    sh = g_x8h + o; sl = g_x8l + o;
    aoff = (rowBase + r) * 2048L + (kc - 8) * 32 + sg * 16;
  }
  cpa16(base + A_HI + d, sh + aoff);
  cpa16(base + A_LO + d, sl + aoff);
  long boff = (bRow + r) * 512L + kc * 32 + sg * 16;
  cpa16(base + B_HI + d, g_w8h + boff);
  cpa16(base + B_LO + d, g_w8l + boff);
}

__global__ __launch_bounds__(NT, 2) void k_step(int t) {
  extern __shared__ signed char sm8[];
  const int tid = threadIdx.x;
  const int z = blockIdx.z, strip = blockIdx.x;
  const long rowBase = (long)blockIdx.y * 128;
  signed char* hnh = g_h8h + ((long)z * 2 + ((t + 1) & 1)) * 4194304;
  signed char* hnl = g_h8l + ((long)z * 2 + ((t + 1) & 1)) * 4194304;
  float* cst = g_c + (long)z * 4194304;
  const long bRow = (long)(z * 8 + strip) * 128;

  const int wid = tid >> 5, lane = tid & 31;
  const int wm = wid & 1, wn = wid >> 1;
  const int qr = lane >> 2, qc = (lane & 3) << 1;

  const int kc0 = (t == 0) ? 8 : 0;   // t=0: x chunks only (h0 = 0)
  const int NK = 16 - kc0;

  float acc[4][4][4];
#pragma unroll
  for (int a = 0; a < 4; a++)
#pragma unroll
    for (int b = 0; b < 4; b++)
#pragma unroll
      for (int q = 0; q < 4; q++) acc[a][b][q] = 0.0f;

  step_stage8(sm8, rowBase, bRow, kc0, t, z, tid);
  CP_COMMIT;

  for (int i = 0; i < NK; i++) {
    const int kc = kc0 + i;
    cp_wait<0>();
    __syncthreads();
    if (i + 1 < NK) {
      step_stage8(sm8 + ((i + 1) & 1) * BUFSZ, rowBase, bRow, kc + 1, t, z, tid);
      CP_COMMIT;
    }
    const signed char* base = sm8 + (i & 1) * BUFSZ;
    const float scale = (kc < 8) ? S_HW : S_XW;
    compute_chunk_i8<true>(base + A_HI, base + A_LO, base + B_HI, base + B_LO,
                           acc, scale, wm, wn, lane);
  }

  // register epilogue: ni -> gate (i,f,g,o) of j = strip*32 + wn*8 + qc
  const int jloc = strip * 32 + wn * 8 + qc;
  const float* bs = g_bsum + z * 1024;
  const float2 bi2 = *(const float2*)(bs + jloc);
  const float2 bf2 = *(const float2*)(bs + 256 + jloc);
  const float2 bg2 = *(const float2*)(bs + 512 + jloc);
  const float2 bo2 = *(const float2*)(bs + 768 + jloc);
#pragma unroll
  for (int mi = 0; mi < 4; mi++) {
#pragma unroll
    for (int hh = 0; hh < 2; hh++) {
      const long n = rowBase + wm * 64 + mi * 16 + qr + hh * 8;
      float2 cp2 = make_float2(0.0f, 0.0f);
      if (t) cp2 = *(const float2*)(cst + n * 256 + jloc);
      const int b = hh * 2;
      float gi0 = acc[mi][0][b] + bi2.x, gi1 = acc[mi][0][b + 1] + bi2.y;
      float gf0 = acc[mi][1][b] + bf2.x, gf1 = acc[mi][1][b + 1] + bf2.y;
      float gg0 = acc[mi][2][b] + bg2.x, gg1 = acc[mi][2][b + 1] + bg2.y;
      float go0 = acc[mi][3][b] + bo2.x, go1 = acc[mi][3][b + 1] + bo2.y;
      float c0 = fsig(gf0) * cp2.x + fsig(gi0) * ftanh(gg0);
      float c1 = fsig(gf1) * cp2.y + fsig(gi1) * ftanh(gg1);
      *(float2*)(cst + n * 256 + jloc) = make_float2(c0, c1);
      float h0 = fsig(go0) * ftanh(c0);
      float h1 = fsig(go1) * ftanh(c1);
      st_q2(hnh + n * 256 + jloc, hnl + n * 256 + jloc, h0, h1);
    }
  }
}

// ---------------------------------------------------------------------------
// Encoder: out = tanh([hl, hr, rel] @ Wenc^T + benc). grid (colTile=2, rowTile=128)
// 256 threads, tile 128x128. K = 576 = 18 chunks; A source hl -> hr -> rel.
// Final h in buf 0 (after t=7 write). int8 path, per-chunk scales.
// ---------------------------------------------------------------------------
__device__ __forceinline__ void enc_stage8(signed char* base, long rowBase,
                                           long bRow, int kc, int tid) {
  int r = tid >> 1, sg = tid & 1;
  int d = SWZ8(r, sg);
  const signed char *sh, *sl;
  long ld; int koff;
  if (kc < 8)       { sh = g_h8h;           sl = g_h8l;           ld = 256; koff = kc * 32; }
  else if (kc < 16) { sh = g_h8h + 8388608; sl = g_h8l + 8388608; ld = 256; koff = (kc - 8) * 32; }
  else              { sh = g_r8h;           sl = g_r8l;           ld = 64;  koff = (kc - 16) * 32; }
  long aoff = (rowBase + r) * ld + koff + sg * 16;
  cpa16(base + A_HI + d, sh + aoff);
  cpa16(base + A_LO + d, sl + aoff);
  long boff = (bRow + r) * 576L + kc * 32 + sg * 16;
  cpa16(base + B_HI + d, g_we8h + boff);
  cpa16(base + B_LO + d, g_we8l + boff);
}

__global__ __launch_bounds__(NT, 2) void k_enc(const float* __restrict__ benc,
                                               float* __restrict__ out) {
  extern __shared__ signed char sm8[];
  const int tid = threadIdx.x;
  const int colTile = blockIdx.x;
  const long rowBase = (long)blockIdx.y * 128;
  const long bRow = (long)colTile * 128;

  const int wid = tid >> 5, lane = tid & 31;
  const int wm = wid & 1, wn = wid >> 1;
  const int qr = lane >> 2, qc = (lane & 3) << 1;

  float acc[4][4][4];
#pragma unroll
  for (int a = 0; a < 4; a++)
#pragma unroll
    for (int b = 0; b < 4; b++)
#pragma unroll
      for (int q = 0; q < 4; q++) acc[a][b][q] = 0.0f;

  enc_stage8(sm8, rowBase, bRow, 0, tid);
  CP_COMMIT;

  for (int i = 0; i < 18; i++) {
    cp_wait<0>();
    __syncthreads();
    if (i + 1 < 18) {
      enc_stage8(sm8 + ((i + 1) & 1) * BUFSZ, rowBase, bRow, i + 1, tid);
      CP_COMMIT;
    }
    const signed char* base = sm8 + (i & 1) * BUFSZ;
    const float scale = (i < 16) ? S_HW : S_XW;  // h chunks vs rel chunks
    compute_chunk_i8<false>(base + A_HI, base + A_LO, base + B_HI, base + B_LO,
                            acc, scale, wm, wn, lane);
  }

#pragma unroll
  for (int mi = 0; mi < 4; mi++) {
#pragma unroll
    for (int hh = 0; hh < 2; hh++) {
      long n = rowBase + wm * 64 + mi * 16 + qr + hh * 8;
#pragma unroll
      for (int ni = 0; ni < 4; ni++) {
        int col = colTile * 128 + wn * 32 + ni * 8 + qc;
        float2 b2 = *(const float2*)(benc + col);
        float v0 = ftanh(acc[mi][ni][hh * 2] + b2.x);
        float v1 = ftanh(acc[mi][ni][hh * 2 + 1] + b2.y);
        *(float2*)(out + n * 256 + col) = make_float2(v0, v1);
      }
    }
  }
}

// ---------------------------------------------------------------------------
extern "C" void kernel_launch(void* const* d_in, const int* in_sizes, int n_in,
                              void* d_out, int out_size) {
  (void)in_sizes; (void)n_in; (void)out_size;
  const float* left  = (const float*)d_in[0];
  const float* right = (const float*)d_in[1];
  const float* rel   = (const float*)d_in[2];
  const float* Wih_l = (const float*)d_in[3];
  const float* Whh_l = (const float*)d_in[4];
  const float* bih_l = (const float*)d_in[5];
  const float* bhh_l = (const float*)d_in[6];
  const float* Wih_r = (const float*)d_in[7];
  const float* Whh_r = (const float*)d_in[8];
  const float* bih_r = (const float*)d_in[9];
  const float* bhh_r = (const float*)d_in[10];
  const float* Wenc  = (const float*)d_in[11];
  const float* benc  = (const float*)d_in[12];
  float* out = (float*)d_out;

  cudaFuncSetAttribute(k_step, cudaFuncAttributeMaxDynamicSharedMemorySize, SMEM_BYTES);
  cudaFuncSetAttribute(k_enc, cudaFuncAttributeMaxDynamicSharedMemorySize, SMEM_BYTES);

  k_split_x<<<65536, NT>>>(left, right);
  k_split_misc<<<8776, NT>>>(Whh_l, Whh_r, Wih_l, Wih_r, Wenc, rel,
                             bih_l, bhh_l, bih_r, bhh_r);
  for (int t = 0; t < 8; t++)
    k_step<<<dim3(8, 128, 2), NT, SMEM_BYTES>>>(t);
  k_enc<<<dim3(2, 128), NT, SMEM_BYTES>>>(benc, out);
}

// round 17
// speedup vs baseline: 4.7925x; 4.7925x over previous
#include <cuda_runtime.h>
#include <cuda_fp16.h>
#include <math.h>

// N=16384 nodes, L=8, D=256, H=256, R=64. Gate order i,f,g,o.
// Fused recurrence: gates_t = [h_{t-1} | x_t] @ [Whh | Wih]^T + b (K=512 GEMM
// per step; t=0 x-only K=256). FP16 2-product scheme: A (h/x/rel) split into
// fp16 hi+lo (22-bit exact), W single fp16 (11-bit) -> A*W = Ah*W + Al*W on
// m16n8k16.f32.f16.f16.f32 (2 MMAs vs bf16's 3). Error = W quantization
// ~1.4e-4, deterministic. XOR-swizzled smem, 2-stage cp.async (48KB/CTA,
// 2 CTAs/SM), single-ldsm4 B fragments, register cell-update epilogue.

#define NT 256

// ------------------------- device scratch (no allocs) -----------------------
__device__ float g_c[8388608];            // [2][16384][256] cell state fp32
__device__ __half g_h16h[16777216];       // [2 lstm][2 buf][16384][256]
__device__ __half g_h16l[16777216];
__device__ __half g_x16h[67108864];       // [2 chain][16384*8 (n*8+l)][256]
__device__ __half g_x16l[67108864];
__device__ __half g_w16[1048576];         // [2][8 strip][128(g*32+jj)][512(Whh|Wih)]
__device__ __half g_we16[147456];         // [256][576]
__device__ __half g_r16h[1048576];        // [16384][64]
__device__ __half g_r16l[1048576];
__device__ float g_bsum[2048];            // [2][1024] bih+bhh

// ------------------------------- helpers ------------------------------------
__device__ __forceinline__ float fsig(float x) {
  return __fdividef(1.0f, 1.0f + __expf(-x));
}
__device__ __forceinline__ float ftanh(float x) {
  return 2.0f * __fdividef(1.0f, 1.0f + __expf(-2.0f * x)) - 1.0f;
}

__device__ __forceinline__ void mma16816h(float* d, const unsigned* a, const unsigned* b) {
  asm volatile(
      "mma.sync.aligned.m16n8k16.row.col.f32.f16.f16.f32 "
      "{%0,%1,%2,%3}, {%4,%5,%6,%7}, {%8,%9}, {%0,%1,%2,%3};\n"
      : "+f"(d[0]), "+f"(d[1]), "+f"(d[2]), "+f"(d[3])
      : "r"(a[0]), "r"(a[1]), "r"(a[2]), "r"(a[3]), "r"(b[0]), "r"(b[1]));
}
__device__ __forceinline__ void ldsm4(unsigned* r, const void* p) {
  unsigned a = (unsigned)__cvta_generic_to_shared(p);
  asm volatile("ldmatrix.sync.aligned.m8n8.x4.shared.b16 {%0,%1,%2,%3}, [%4];\n"
               : "=r"(r[0]), "=r"(r[1]), "=r"(r[2]), "=r"(r[3]) : "r"(a));
}
__device__ __forceinline__ void cpa16(void* dst, const void* src) {
  unsigned s = (unsigned)__cvta_generic_to_shared(dst);
  asm volatile("cp.async.cg.shared.global [%0], [%1], 16;\n" :: "r"(s), "l"(src));
}
#define CP_COMMIT asm volatile("cp.async.commit_group;\n")
template <int N>
__device__ __forceinline__ void cp_wait() {
  asm volatile("cp.async.wait_group %0;\n" :: "n"(N));
}

// XOR-swizzled smem layout: array [128 rows][32 fp16] (64B rows, no pad).
// Element offset for (row r, 16B-seg s in 0..3): r*32 + ((s ^ ((r>>1)&3))<<3).
#define SWZ(r, s) ((r) * 32 + ((((s) ^ (((r) >> 1) & 3))) << 3))
#define A_HI 0
#define A_LO 4096
#define B_W  8192
#define BUFSZ 12288      // elems per stage (24KB)
#define SMEM_BYTES 49152 // 2 stages x 24KB

// stage one 128x32 fp16 chunk: 512 16B segs, 2 per thread
__device__ __forceinline__ void stage_arr(__half* d, const __half* s,
                                          long rowBase, int ld, int koff, int tid) {
#pragma unroll
  for (int i = 0; i < 2; i++) {
    int f = tid + i * NT;
    int row = f >> 2, seg = f & 3;
    cpa16(d + SWZ(row, seg), s + (rowBase + row) * (long)ld + koff + seg * 8);
  }
}

// GM=true: B smem row c = ni*32 + wn*8 + lr (gate-major); false: wn*32 + ni*8.
// B: one ldsm4 per ni, lane-group g -> seg g => regs {0,1}=k0-15, {2,3}=k16-31.
// A: per (mi, limb, kk) ldsm4 (rows+8 and k+8 via lane groups). 2 products:
// Ah*W then Al*W (A regs reused between products; same-acc separation 16).
template <bool GM>
__device__ __forceinline__ void compute_chunk_h(const __half* ahi, const __half* alo,
                                                const __half* bsm, float acc[4][4][4],
                                                int wm, int wn, int lane) {
  const int lr = lane & 7;
  const int arofs = ((lane >> 3) & 1) * 8;
  const int akb = (lane >> 4) * 8;
  const int bsg = lane >> 3;  // 0..3 -> segs 0..3
  unsigned bb[4][4];
#pragma unroll
  for (int ni = 0; ni < 4; ni++) {
    int c = (GM ? ni * 32 + wn * 8 : wn * 32 + ni * 8) + lr;
    ldsm4(bb[ni], bsm + SWZ(c, bsg));
  }
#pragma unroll
  for (int kk = 0; kk < 32; kk += 16) {
    const int s = (kk + akb) >> 3;
    const int bk = kk >> 3;  // 0 or 2
    unsigned aa[4][4];
#pragma unroll
    for (int mi = 0; mi < 4; mi++) {
      int r = wm * 64 + mi * 16 + lr + arofs;
      ldsm4(aa[mi], ahi + SWZ(r, s));
    }
#pragma unroll
    for (int mi = 0; mi < 4; mi++)
#pragma unroll
      for (int ni = 0; ni < 4; ni++) mma16816h(acc[mi][ni], aa[mi], &bb[ni][bk]);
#pragma unroll
    for (int mi = 0; mi < 4; mi++) {
      int r = wm * 64 + mi * 16 + lr + arofs;
      ldsm4(aa[mi], alo + SWZ(r, s));
    }
#pragma unroll
    for (int mi = 0; mi < 4; mi++)
#pragma unroll
      for (int ni = 0; ni < 4; ni++) mma16816h(acc[mi][ni], aa[mi], &bb[ni][bk]);
  }
}

// fp16 hi/lo split store for 2 adjacent values
__device__ __forceinline__ void st_split2h(__half* ph, __half* pl, float x, float y) {
  __half xh = __float2half_rn(x), yh = __float2half_rn(y);
  __half2 t; t.x = xh; t.y = yh;
  *(__half2*)ph = t;
  __half2 u;
  u.x = __float2half_rn(x - __half2float(xh));
  u.y = __float2half_rn(y - __half2float(yh));
  *(__half2*)pl = u;
}

// ---------------------------------------------------------------------------
// Split kernels (run every call; deterministic)
// ---------------------------------------------------------------------------
__global__ void k_split_x(const float* __restrict__ xl, const float* __restrict__ xr) {
  long i = (long)blockIdx.x * NT + threadIdx.x;  // [0, 16777216) float4 groups
  long chain = i >> 23;
  long j = i & 8388607;
  float4 v = *(const float4*)((chain ? xr : xl) + j * 4);
  long o = chain * 33554432 + j * 4;
  st_split2h(g_x16h + o, g_x16l + o, v.x, v.y);
  st_split2h(g_x16h + o + 2, g_x16l + o + 2, v.z, v.w);
}

__global__ void k_split_misc(const float* __restrict__ Whh_l, const float* __restrict__ Whh_r,
                             const float* __restrict__ Wih_l, const float* __restrict__ Wih_r,
                             const float* __restrict__ Wenc, const float* __restrict__ rel,
                             const float* __restrict__ bih_l, const float* __restrict__ bhh_l,
                             const float* __restrict__ bih_r, const float* __restrict__ bhh_r) {
  long idx = (long)blockIdx.x * NT + threadIdx.x;
  if (idx < 1048576) {
    // Wcomb gather: dst (((z*8+strip)*128 + (g*32+jj))*512 + k
    int k = (int)(idx & 511);
    long r2 = idx >> 9;
    int row = (int)(r2 & 127);
    int zs = (int)(r2 >> 7);
    int strip = zs & 7, z = zs >> 3;
    int g = row >> 5, jj = row & 31;
    long wrow = (long)(g * 256 + strip * 32 + jj) * 256;
    float v;
    if (k < 256) v = (z ? Whh_r : Whh_l)[wrow + k];
    else         v = (z ? Wih_r : Wih_l)[wrow + k - 256];
    g_w16[idx] = __float2half_rn(v);
  } else if (idx < 1196032) {
    long j = idx - 1048576;
    g_we16[j] = __float2half_rn(Wenc[j]);
  } else if (idx < 2244608) {
    long j = idx - 1196032;
    float v = rel[j];
    __half h = __float2half_rn(v);
    g_r16h[j] = h;
    g_r16l[j] = __float2half_rn(v - __half2float(h));
  } else if (idx < 2246656) {
    long j = idx - 2244608;  // [0,2048)
    int z = (int)(j >> 10);
    int cc = (int)(j & 1023);
    g_bsum[j] = (z ? bih_r[cc] : bih_l[cc]) + (z ? bhh_r[cc] : bhh_l[cc]);
  }
}

// ---------------------------------------------------------------------------
// Fused recurrent step t (0..7): gates = [h_{t-1} | x_t] @ Wcomb^T + bsum.
// grid (strip=8, rowTile=128, z=2), 256 threads, 2 CTAs/SM. K=512 = 16 chunks
// (8 h + 8 x); t=0 skips the h chunks (h0=0). 2-stage cp.async pipeline.
// Gate-major fragment map (ni=gate): register cell-update epilogue.
// ---------------------------------------------------------------------------
__device__ __forceinline__ void step_stage_full(__half* base, long rowBase,
                                                long bRow, int kc, int t, int z, int tid) {
  if (kc < 8) {
    long off = ((long)z * 2 + (t & 1)) * 4194304;
    stage_arr(base + A_HI, g_h16h + off, rowBase, 256, kc * 32, tid);
    stage_arr(base + A_LO, g_h16l + off, rowBase, 256, kc * 32, tid);
  } else {
    long off = (long)z * 33554432 + t * 256;  // row n -> (n*8+t)*256
    stage_arr(base + A_HI, g_x16h + off, rowBase, 2048, (kc - 8) * 32, tid);
    stage_arr(base + A_LO, g_x16l + off, rowBase, 2048, (kc - 8) * 32, tid);
  }
  stage_arr(base + B_W, g_w16, bRow, 512, kc * 32, tid);
}

__global__ __launch_bounds__(NT, 2) void k_step(int t) {
  extern __shared__ __half sm[];
  const int tid = threadIdx.x;
  const int z = blockIdx.z, strip = blockIdx.x;
  const long rowBase = (long)blockIdx.y * 128;
  __half* hnh = g_h16h + ((long)z * 2 + ((t + 1) & 1)) * 4194304;
  __half* hnl = g_h16l + ((long)z * 2 + ((t + 1) & 1)) * 4194304;
  float* cst = g_c + (long)z * 4194304;
  const long bRow = (long)(z * 8 + strip) * 128;

  const int wid = tid >> 5, lane = tid & 31;
  const int wm = wid & 1, wn = wid >> 1;
  const int qr = lane >> 2, qc = (lane & 3) << 1;

  const int kc0 = (t == 0) ? 8 : 0;   // t=0: x chunks only (h0 = 0)
  const int NK = 16 - kc0;

  float acc[4][4][4];
#pragma unroll
  for (int a = 0; a < 4; a++)
#pragma unroll
    for (int b = 0; b < 4; b++)
#pragma unroll
      for (int q = 0; q < 4; q++) acc[a][b][q] = 0.0f;

  step_stage_full(sm, rowBase, bRow, kc0, t, z, tid);
  CP_COMMIT;

  for (int i = 0; i < NK; i++) {
    cp_wait<0>();
    __syncthreads();
    if (i + 1 < NK) {
      step_stage_full(sm + ((i + 1) & 1) * BUFSZ, rowBase, bRow, kc0 + i + 1, t, z, tid);
      CP_COMMIT;
    }
    const __half* base = sm + (i & 1) * BUFSZ;
    compute_chunk_h<true>(base + A_HI, base + A_LO, base + B_W, acc, wm, wn, lane);
  }

  // register epilogue: ni -> gate (i,f,g,o) of j = strip*32 + wn*8 + qc
  const int jloc = strip * 32 + wn * 8 + qc;
  const float* bs = g_bsum + z * 1024;
  const float2 bi2 = *(const float2*)(bs + jloc);
  const float2 bf2 = *(const float2*)(bs + 256 + jloc);
  const float2 bg2 = *(const float2*)(bs + 512 + jloc);
  const float2 bo2 = *(const float2*)(bs + 768 + jloc);
#pragma unroll
  for (int mi = 0; mi < 4; mi++) {
#pragma unroll
    for (int hh = 0; hh < 2; hh++) {
      const long n = rowBase + wm * 64 + mi * 16 + qr + hh * 8;
      float2 cp2 = make_float2(0.0f, 0.0f);
      if (t) cp2 = *(const float2*)(cst + n * 256 + jloc);
      const int b = hh * 2;
      float gi0 = acc[mi][0][b] + bi2.x, gi1 = acc[mi][0][b + 1] + bi2.y;
      float gf0 = acc[mi][1][b] + bf2.x, gf1 = acc[mi][1][b + 1] + bf2.y;
      float gg0 = acc[mi][2][b] + bg2.x, gg1 = acc[mi][2][b + 1] + bg2.y;
      float go0 = acc[mi][3][b] + bo2.x, go1 = acc[mi][3][b + 1] + bo2.y;
      float c0 = fsig(gf0) * cp2.x + fsig(gi0) * ftanh(gg0);
      float c1 = fsig(gf1) * cp2.y + fsig(gi1) * ftanh(gg1);
      *(float2*)(cst + n * 256 + jloc) = make_float2(c0, c1);
      float h0 = fsig(go0) * ftanh(c0);
      float h1 = fsig(go1) * ftanh(c1);
      st_split2h(hnh + n * 256 + jloc, hnl + n * 256 + jloc, h0, h1);
    }
  }
}

// ---------------------------------------------------------------------------
// Encoder: out = tanh([hl, hr, rel] @ Wenc^T + benc). grid (colTile=2, rowTile=128)
// 256 threads, tile 128x128. K = 576 = 18 chunks; A source hl -> hr -> rel.
// Final h in buf 0 (after t=7 write).
// ---------------------------------------------------------------------------
__device__ __forceinline__ void enc_stage_full(__half* base, long rowBase,
                                               long bRow, int kc, int tid) {
  const __half *sh, *sl;
  int ld, koff;
  if (kc < 8)       { sh = g_h16h;           sl = g_h16l;           ld = 256; koff = kc * 32; }
  else if (kc < 16) { sh = g_h16h + 8388608; sl = g_h16l + 8388608; ld = 256; koff = (kc - 8) * 32; }
  else              { sh = g_r16h;           sl = g_r16l;           ld = 64;  koff = (kc - 16) * 32; }
  stage_arr(base + A_HI, sh, rowBase, ld, koff, tid);
  stage_arr(base + A_LO, sl, rowBase, ld, koff, tid);
  stage_arr(base + B_W, g_we16, bRow, 576, kc * 32, tid);
}

__global__ __launch_bounds__(NT, 2) void k_enc(const float* __restrict__ benc,
                                               float* __restrict__ out) {
  extern __shared__ __half sm[];
  const int tid = threadIdx.x;
  const int colTile = blockIdx.x;
  const long rowBase = (long)blockIdx.y * 128;
  const long bRow = (long)colTile * 128;

  const int wid = tid >> 5, lane = tid & 31;
  const int wm = wid & 1, wn = wid >> 1;
  const int qr = lane >> 2, qc = (lane & 3) << 1;

  float acc[4][4][4];
#pragma unroll
  for (int a = 0; a < 4; a++)
#pragma unroll
    for (int b = 0; b < 4; b++)
#pragma unroll
      for (int q = 0; q < 4; q++) acc[a][b][q] = 0.0f;

  enc_stage_full(sm, rowBase, bRow, 0, tid);
  CP_COMMIT;

  for (int i = 0; i < 18; i++) {
    cp_wait<0>();
    __syncthreads();
    if (i + 1 < 18) {
      enc_stage_full(sm + ((i + 1) & 1) * BUFSZ, rowBase, bRow, i + 1, tid);
      CP_COMMIT;
    }
    const __half* base = sm + (i & 1) * BUFSZ;
    compute_chunk_h<false>(base + A_HI, base + A_LO, base + B_W, acc, wm, wn, lane);
  }

#pragma unroll
  for (int mi = 0; mi < 4; mi++) {
#pragma unroll
    for (int hh = 0; hh < 2; hh++) {
      long n = rowBase + wm * 64 + mi * 16 + qr + hh * 8;
#pragma unroll
      for (int ni = 0; ni < 4; ni++) {
        int col = colTile * 128 + wn * 32 + ni * 8 + qc;
        float2 b2 = *(const float2*)(benc + col);
        float v0 = ftanh(acc[mi][ni][hh * 2] + b2.x);
        float v1 = ftanh(acc[mi][ni][hh * 2 + 1] + b2.y);
        *(float2*)(out + n * 256 + col) = make_float2(v0, v1);
      }
    }
  }
}

// ---------------------------------------------------------------------------
extern "C" void kernel_launch(void* const* d_in, const int* in_sizes, int n_in,
                              void* d_out, int out_size) {
  (void)in_sizes; (void)n_in; (void)out_size;
  const float* left  = (const float*)d_in[0];
  const float* right = (const float*)d_in[1];
  const float* rel   = (const float*)d_in[2];
  const float* Wih_l = (const float*)d_in[3];
  const float* Whh_l = (const float*)d_in[4];
  const float* bih_l = (const float*)d_in[5];
  const float* bhh_l = (const float*)d_in[6];
  const float* Wih_r = (const float*)d_in[7];
  const float* Whh_r = (const float*)d_in[8];
  const float* bih_r = (const float*)d_in[9];
  const float* bhh_r = (const float*)d_in[10];
  const float* Wenc  = (const float*)d_in[11];
  const float* benc  = (const float*)d_in[12];
  float* out = (float*)d_out;

  cudaFuncSetAttribute(k_step, cudaFuncAttributeMaxDynamicSharedMemorySize, SMEM_BYTES);
  cudaFuncSetAttribute(k_enc, cudaFuncAttributeMaxDynamicSharedMemorySize, SMEM_BYTES);

  k_split_x<<<65536, NT>>>(left, right);
  k_split_misc<<<8776, NT>>>(Whh_l, Whh_r, Wih_l, Wih_r, Wenc, rel,
                             bih_l, bhh_l, bih_r, bhh_r);
  for (int t = 0; t < 8; t++)
    k_step<<<dim3(8, 128, 2), NT, SMEM_BYTES>>>(t);
  k_enc<<<dim3(2, 128), NT, SMEM_BYTES>>>(benc, out);
}